// round 1
// baseline (speedup 1.0000x reference)
#include <cuda_runtime.h>
#include <cuda_bf16.h>
#include <cstdint>

// Problem constants (fixed by the dataset)
#define BATCH 16
#define TT    8192
#define HH    256
#define HQ    64
#define KSLOT 128
#define BS    64                 // token block size for partial sums
#define NBLK  (TT / BS)          // 128
#define SWPAD 8                  // bf16 elements of row padding (16B) -> conflict-free frags
#define SROW  (HH + SWPAD)       // 264

// Scratch (static device allocations are the allowed mechanism)
__device__ float d_e[BATCH * TT];            // exp(score) per token
__device__ float d_S[BATCH * NBLK * HH];     // per-block sum of e*x
__device__ float d_E[BATCH * NBLK];          // per-block sum of e

// Dynamic smem layout for pass A:
//   sW : bf16 [HQ][SROW]   (W1 transposed: [n][k])
//   sX : bf16 [BS][SROW]   (token tile)
//   sE : float[BS]
//   sB1: float[HQ]
//   sW2: float[HQ]
#define SMEM_A_BYTES (HQ*SROW*2 + BS*SROW*2 + BS*4 + HQ*4 + HQ*4)

__global__ void __launch_bounds__(128) pass_a_kernel(
    const float* __restrict__ x,
    const float* __restrict__ W1,
    const float* __restrict__ b1,
    const float* __restrict__ W2,
    const float* __restrict__ b2)
{
    extern __shared__ char smem[];
    __nv_bfloat16* sW = (__nv_bfloat16*)smem;            // HQ*SROW
    __nv_bfloat16* sX = sW + HQ * SROW;                  // BS*SROW
    float* sE  = (float*)(sX + BS * SROW);
    float* sB1 = sE + BS;
    float* sW2 = sB1 + HQ;

    const int blk  = blockIdx.x;      // 0..NBLK-1
    const int b    = blockIdx.y;      // 0..BATCH-1
    const int tid  = threadIdx.x;     // 0..127
    const int warp = tid >> 5;
    const int lane = tid & 31;

    const float* xblk = x + ((size_t)b * TT + (size_t)blk * BS) * HH;

    // --- load W1 transposed (bf16), b1, W2 ---
    for (int i = tid; i < HH * HQ; i += 128) {
        int k = i / HQ, n = i % HQ;
        sW[n * SROW + k] = __float2bfloat16(W1[i]);
    }
    if (tid < HQ) { sB1[tid] = b1[tid]; sW2[tid] = W2[tid]; }

    // --- load token tile, convert to bf16 ---
    for (int i = tid; i < BS * HH; i += 128) {
        int r = i / HH, c = i % HH;
        sX[r * SROW + c] = __float2bfloat16(xblk[i]);
    }
    __syncthreads();

    // --- MMA: each warp computes 16 tokens x 64 hidden (preactivations) ---
    float acc[8][4];
    #pragma unroll
    for (int nt = 0; nt < 8; nt++)
        #pragma unroll
        for (int i = 0; i < 4; i++) acc[nt][i] = 0.f;

    const int g = lane >> 2;          // group id 0..7
    const int m = lane & 3;           // id in group 0..3
    const int row0 = warp * 16 + g;   // token row (first half)

    #pragma unroll
    for (int kt = 0; kt < HH / 16; kt++) {
        const int kb = kt * 16 + m * 2;
        uint32_t a0 = *(const uint32_t*)&sX[(row0)     * SROW + kb];
        uint32_t a1 = *(const uint32_t*)&sX[(row0 + 8) * SROW + kb];
        uint32_t a2 = *(const uint32_t*)&sX[(row0)     * SROW + kb + 8];
        uint32_t a3 = *(const uint32_t*)&sX[(row0 + 8) * SROW + kb + 8];
        #pragma unroll
        for (int nt = 0; nt < 8; nt++) {
            const int n = nt * 8 + g;
            uint32_t bf0 = *(const uint32_t*)&sW[n * SROW + kb];
            uint32_t bf1 = *(const uint32_t*)&sW[n * SROW + kb + 8];
            asm volatile(
                "mma.sync.aligned.m16n8k16.row.col.f32.bf16.bf16.f32 "
                "{%0,%1,%2,%3},{%4,%5,%6,%7},{%8,%9},{%0,%1,%2,%3};"
                : "+f"(acc[nt][0]), "+f"(acc[nt][1]),
                  "+f"(acc[nt][2]), "+f"(acc[nt][3])
                : "r"(a0), "r"(a1), "r"(a2), "r"(a3), "r"(bf0), "r"(bf1));
        }
    }

    // --- tanh + dot with W2 -> per-token score ---
    float s0 = 0.f, s1 = 0.f;
    #pragma unroll
    for (int nt = 0; nt < 8; nt++) {
        const int c0 = nt * 8 + m * 2;
        const int c1 = c0 + 1;
        float h;
        h = tanhf(acc[nt][0] + sB1[c0]); s0 += h * sW2[c0];
        h = tanhf(acc[nt][1] + sB1[c1]); s0 += h * sW2[c1];
        h = tanhf(acc[nt][2] + sB1[c0]); s1 += h * sW2[c0];
        h = tanhf(acc[nt][3] + sB1[c1]); s1 += h * sW2[c1];
    }
    // reduce across the 4 lanes of each group (low 2 lane bits)
    s0 += __shfl_xor_sync(0xffffffffu, s0, 1);
    s0 += __shfl_xor_sync(0xffffffffu, s0, 2);
    s1 += __shfl_xor_sync(0xffffffffu, s1, 1);
    s1 += __shfl_xor_sync(0xffffffffu, s1, 2);

    const float bb2 = b2[0];
    const float e0 = __expf(s0 + bb2);
    const float e1 = __expf(s1 + bb2);
    if (m == 0) {
        sE[row0]     = e0;
        sE[row0 + 8] = e1;
        d_e[b * TT + blk * BS + row0]     = e0;
        d_e[b * TT + blk * BS + row0 + 8] = e1;
    }
    __syncthreads();

    // --- block partial sums in fp32 (re-read x from gmem: L1/L2 hits) ---
    float accA = 0.f, accB = 0.f, esum = 0.f;
    #pragma unroll 4
    for (int t = 0; t < BS; t++) {
        const float e = sE[t];
        accA += e * xblk[t * HH + tid];
        accB += e * xblk[t * HH + tid + 128];
        esum += e;
    }
    d_S[((size_t)b * NBLK + blk) * HH + tid]       = accA;
    d_S[((size_t)b * NBLK + blk) * HH + tid + 128] = accB;
    if (tid == 0) d_E[b * NBLK + blk] = esum;
}

__global__ void __launch_bounds__(256) pass_b_kernel(
    const float* __restrict__ x,
    const int*   __restrict__ boundaries,
    const int*   __restrict__ slot_mask,
    float*       __restrict__ out)
{
    const int k   = blockIdx.x;       // 0..KSLOT-1
    const int b   = blockIdx.y;       // 0..BATCH-1
    const int tid = threadIdx.x;      // 0..255 (== h index)

    const int sidx  = b * KSLOT + k;
    const int start = boundaries[sidx * 2];
    const int end   = boundaries[sidx * 2 + 1];
    const int mask  = slot_mask[sidx];

    float* o = out + (size_t)sidx * HH;

    if (mask <= 0 || start >= end) { o[tid] = 0.f; return; }

    const float* xb = x + (size_t)b * TT * HH;
    const float* eb = d_e + b * TT;

    float acc = 0.f, den = 0.f;

    const int fb = (start + BS - 1) / BS;  // first full block
    const int lb = end / BS;               // one past last full block

    if (fb < lb) {
        const float* Sb = d_S + (size_t)b * NBLK * HH;
        #pragma unroll 2
        for (int i = fb; i < lb; i++) {
            acc += Sb[(size_t)i * HH + tid];
            den += d_E[b * NBLK + i];
        }
        const int le = fb * BS;            // left edge [start, le)
        #pragma unroll 4
        for (int t = start; t < le; t++) {
            const float e = eb[t];
            acc += e * xb[(size_t)t * HH + tid];
            den += e;
        }
        const int rs = lb * BS;            // right edge [rs, end)
        #pragma unroll 4
        for (int t = rs; t < end; t++) {
            const float e = eb[t];
            acc += e * xb[(size_t)t * HH + tid];
            den += e;
        }
    } else {
        #pragma unroll 4
        for (int t = start; t < end; t++) {
            const float e = eb[t];
            acc += e * xb[(size_t)t * HH + tid];
            den += e;
        }
    }

    o[tid] = acc / den;  // den > 0 guaranteed: end > start and e_t > 0
}

extern "C" void kernel_launch(void* const* d_in, const int* in_sizes, int n_in,
                              void* d_out, int out_size)
{
    const float* x          = (const float*)d_in[0];
    const int*   boundaries = (const int*)d_in[1];
    const int*   slot_mask  = (const int*)d_in[2];
    const float* W1         = (const float*)d_in[3];
    const float* b1         = (const float*)d_in[4];
    const float* W2         = (const float*)d_in[5];
    const float* b2         = (const float*)d_in[6];
    float* out = (float*)d_out;

    cudaFuncSetAttribute(pass_a_kernel,
                         cudaFuncAttributeMaxDynamicSharedMemorySize,
                         SMEM_A_BYTES);

    pass_a_kernel<<<dim3(NBLK, BATCH), 128, SMEM_A_BYTES>>>(x, W1, b1, W2, b2);
    pass_b_kernel<<<dim3(KSLOT, BATCH), 256>>>(x, boundaries, slot_mask, out);
}

// round 2
// speedup vs baseline: 1.9417x; 1.9417x over previous
#include <cuda_runtime.h>
#include <cuda_bf16.h>
#include <cstdint>

// Problem constants (fixed by the dataset)
#define BATCH 16
#define TT    8192
#define HH    256
#define HQ    64
#define KSLOT 128
#define BS    64                 // token block size for partial sums
#define NBLK  (TT / BS)          // 128
#define NTILES (BATCH * NBLK)    // 2048
#define SROWA 260                // fp32 words per smem row (256 + 4 pad) -> conflict-free

// Scratch
__device__ float d_e[BATCH * TT];            // exp(score) per token
__device__ float d_S[BATCH * NBLK * HH];     // per-block sum of e*x
__device__ float d_E[BATCH * NBLK];          // per-block sum of e

__device__ __forceinline__ float tf32r(float x) {
    float r; asm("cvt.rna.tf32.f32 %0, %1;" : "=f"(r) : "f"(x)); return r;
}
__device__ __forceinline__ float tanha(float x) {
    float r; asm("tanh.approx.f32 %0, %1;" : "=f"(r) : "f"(x)); return r;
}

// smem: sX fp32[64][SROWA] | sE[64] | sP[64][8]
#define SMEM_A_BYTES ((64 * SROWA + 64 + 64 * 8) * 4)

__global__ void __launch_bounds__(256, 2) pass_a_kernel(
    const float* __restrict__ x,
    const float* __restrict__ W1,
    const float* __restrict__ b1,
    const float* __restrict__ W2,
    const float* __restrict__ b2)
{
    extern __shared__ float sm[];
    float* sX = sm;                       // 64*SROWA
    float* sE = sX + 64 * SROWA;          // 64
    float* sP = sE + 64;                  // 64*8 (token-major partials)

    const int tid  = threadIdx.x;
    const int warp = tid >> 5;            // 0..7, owns n-cols [warp*8, warp*8+8)
    const int lane = tid & 31;
    const int g    = lane >> 2;           // group id 0..7
    const int q    = lane & 3;            // id in group 0..3
    const int n0   = warp * 8;

    // Per-thread epilogue constants (cols c0, c1 of this thread's accumulators)
    const int c0 = n0 + q * 2;
    const float w2_0 = W2[c0],   w2_1 = W2[c0 + 1];
    const float b1_0 = b1[c0],   b1_1 = b1[c0 + 1];
    const float bb2  = b2[0];

    // Load W1 once into tf32 register B-fragments: Breg[kt][2], kt covers k=kt*8..kt*8+7
    uint32_t Breg[32][2];
    #pragma unroll
    for (int kt = 0; kt < 32; kt++) {
        const int k0 = kt * 8 + q;
        Breg[kt][0] = __float_as_uint(tf32r(W1[(k0)     * HQ + n0 + g]));
        Breg[kt][1] = __float_as_uint(tf32r(W1[(k0 + 4) * HQ + n0 + g]));
    }

    for (int tile = blockIdx.x; tile < NTILES; tile += gridDim.x) {
        const int b   = tile >> 7;        // NBLK = 128
        const int blk = tile & 127;
        const float* xblk = x + ((size_t)b * TT + (size_t)blk * BS) * HH;

        __syncthreads();                  // previous tile fully consumed

        // --- load x tile (float4), round to tf32 at store ---
        #pragma unroll
        for (int i = 0; i < 16; i++) {
            const int off = i * 1024 + tid * 4;
            float4 v = *(const float4*)(xblk + off);
            v.x = tf32r(v.x); v.y = tf32r(v.y); v.z = tf32r(v.z); v.w = tf32r(v.w);
            const int r = off >> 8, c = off & 255;
            *(float4*)&sX[r * SROWA + c] = v;
        }
        __syncthreads();

        // --- MMA: warp computes all 64 tokens x its 8 n-cols ---
        float acc[4][4];
        #pragma unroll
        for (int m = 0; m < 4; m++)
            #pragma unroll
            for (int i = 0; i < 4; i++) acc[m][i] = 0.f;

        #pragma unroll
        for (int kt = 0; kt < 32; kt++) {
            const int kb = kt * 8 + q;
            #pragma unroll
            for (int m = 0; m < 4; m++) {
                const int r = m * 16 + g;
                uint32_t a0 = __float_as_uint(sX[(r)     * SROWA + kb]);
                uint32_t a1 = __float_as_uint(sX[(r + 8) * SROWA + kb]);
                uint32_t a2 = __float_as_uint(sX[(r)     * SROWA + kb + 4]);
                uint32_t a3 = __float_as_uint(sX[(r + 8) * SROWA + kb + 4]);
                asm volatile(
                    "mma.sync.aligned.m16n8k8.row.col.f32.tf32.tf32.f32 "
                    "{%0,%1,%2,%3},{%4,%5,%6,%7},{%8,%9},{%0,%1,%2,%3};"
                    : "+f"(acc[m][0]), "+f"(acc[m][1]),
                      "+f"(acc[m][2]), "+f"(acc[m][3])
                    : "r"(a0), "r"(a1), "r"(a2), "r"(a3),
                      "r"(Breg[kt][0]), "r"(Breg[kt][1]));
            }
        }

        // --- epilogue: tanh + W2-dot -> per-warp partial score per token ---
        #pragma unroll
        for (int m = 0; m < 4; m++) {
            float p0 = tanha(acc[m][0] + b1_0) * w2_0 + tanha(acc[m][1] + b1_1) * w2_1;
            float p1 = tanha(acc[m][2] + b1_0) * w2_0 + tanha(acc[m][3] + b1_1) * w2_1;
            p0 += __shfl_xor_sync(0xffffffffu, p0, 1);
            p0 += __shfl_xor_sync(0xffffffffu, p0, 2);
            p1 += __shfl_xor_sync(0xffffffffu, p1, 1);
            p1 += __shfl_xor_sync(0xffffffffu, p1, 2);
            if (q == 0) {
                sP[(m * 16 + g)     * 8 + warp] = p0;
                sP[(m * 16 + g + 8) * 8 + warp] = p1;
            }
        }
        __syncthreads();

        // --- reduce 8 warps, exp, publish e ---
        if (tid < 64) {
            float s = bb2;
            #pragma unroll
            for (int w = 0; w < 8; w++) s += sP[tid * 8 + w];
            const float e = __expf(s);
            sE[tid] = e;
            d_e[b * TT + blk * BS + tid] = e;
        }
        __syncthreads();

        // --- block partial sums from smem (fp32, tf32-rounded x) ---
        float a = 0.f, den = 0.f;
        #pragma unroll 8
        for (int t = 0; t < BS; t++) {
            const float e = sE[t];
            a   += e * sX[t * SROWA + tid];
            den += e;
        }
        d_S[((size_t)b * NBLK + blk) * HH + tid] = a;
        if (tid == 0) d_E[b * NBLK + blk] = den;
    }
}

__global__ void __launch_bounds__(256) pass_b_kernel(
    const float* __restrict__ x,
    const int*   __restrict__ boundaries,
    const int*   __restrict__ slot_mask,
    float*       __restrict__ out)
{
    const int k   = blockIdx.x;       // 0..KSLOT-1
    const int b   = blockIdx.y;       // 0..BATCH-1
    const int tid = threadIdx.x;      // == h index

    const int sidx  = b * KSLOT + k;
    const int start = boundaries[sidx * 2];
    const int end   = boundaries[sidx * 2 + 1];
    const int mask  = slot_mask[sidx];

    float* o = out + (size_t)sidx * HH;
    if (mask <= 0 || start >= end) { o[tid] = 0.f; return; }

    const float* xb = x + (size_t)b * TT * HH;
    const float* eb = d_e + b * TT;
    const float* Sb = d_S + (size_t)b * NBLK * HH;
    const float* Eb = d_E + b * NBLK;

    float acc = 0.f, den = 0.f;

    const int fb = (start + BS - 1) / BS;  // first full block
    const int lb = end / BS;               // one past last full block

    if (fb < lb) {
        // full blocks, 4-wide unroll with independent chains
        float a0 = 0.f, a1 = 0.f, a2 = 0.f, a3 = 0.f;
        float d0 = 0.f, d1 = 0.f, d2 = 0.f, d3 = 0.f;
        int i = fb;
        for (; i + 4 <= lb; i += 4) {
            a0 += Sb[(size_t)(i + 0) * HH + tid]; d0 += Eb[i + 0];
            a1 += Sb[(size_t)(i + 1) * HH + tid]; d1 += Eb[i + 1];
            a2 += Sb[(size_t)(i + 2) * HH + tid]; d2 += Eb[i + 2];
            a3 += Sb[(size_t)(i + 3) * HH + tid]; d3 += Eb[i + 3];
        }
        for (; i < lb; i++) { a0 += Sb[(size_t)i * HH + tid]; d0 += Eb[i]; }
        acc = (a0 + a1) + (a2 + a3);
        den = (d0 + d1) + (d2 + d3);

        // left edge [start, fb*BS)
        {
            const int le = fb * BS;
            float ea = 0.f, eb2 = 0.f, da = 0.f, db = 0.f;
            int t = start;
            for (; t + 2 <= le; t += 2) {
                const float e0 = eb[t], e1 = eb[t + 1];
                ea  += e0 * xb[(size_t)(t)     * HH + tid]; da += e0;
                eb2 += e1 * xb[(size_t)(t + 1) * HH + tid]; db += e1;
            }
            for (; t < le; t++) { const float e = eb[t]; ea += e * xb[(size_t)t * HH + tid]; da += e; }
            acc += ea + eb2; den += da + db;
        }
        // right edge [lb*BS, end)
        {
            const int rs = lb * BS;
            float ea = 0.f, eb2 = 0.f, da = 0.f, db = 0.f;
            int t = rs;
            for (; t + 2 <= end; t += 2) {
                const float e0 = eb[t], e1 = eb[t + 1];
                ea  += e0 * xb[(size_t)(t)     * HH + tid]; da += e0;
                eb2 += e1 * xb[(size_t)(t + 1) * HH + tid]; db += e1;
            }
            for (; t < end; t++) { const float e = eb[t]; ea += e * xb[(size_t)t * HH + tid]; da += e; }
            acc += ea + eb2; den += da + db;
        }
    } else {
        // short slot entirely inside one block
        float ea = 0.f, eb2 = 0.f, da = 0.f, db = 0.f;
        int t = start;
        for (; t + 2 <= end; t += 2) {
            const float e0 = eb[t], e1 = eb[t + 1];
            ea  += e0 * xb[(size_t)(t)     * HH + tid]; da += e0;
            eb2 += e1 * xb[(size_t)(t + 1) * HH + tid]; db += e1;
        }
        for (; t < end; t++) { const float e = eb[t]; ea += e * xb[(size_t)t * HH + tid]; da += e; }
        acc = ea + eb2; den = da + db;
    }

    o[tid] = acc / den;  // den > 0 guaranteed: end > start and e_t > 0
}

extern "C" void kernel_launch(void* const* d_in, const int* in_sizes, int n_in,
                              void* d_out, int out_size)
{
    const float* x          = (const float*)d_in[0];
    const int*   boundaries = (const int*)d_in[1];
    const int*   slot_mask  = (const int*)d_in[2];
    const float* W1         = (const float*)d_in[3];
    const float* b1         = (const float*)d_in[4];
    const float* W2         = (const float*)d_in[5];
    const float* b2         = (const float*)d_in[6];
    float* out = (float*)d_out;

    cudaFuncSetAttribute(pass_a_kernel,
                         cudaFuncAttributeMaxDynamicSharedMemorySize,
                         SMEM_A_BYTES);

    pass_a_kernel<<<296, 256, SMEM_A_BYTES>>>(x, W1, b1, W2, b2);
    pass_b_kernel<<<dim3(KSLOT, BATCH), 256>>>(x, boundaries, slot_mask, out);
}